// round 12
// baseline (speedup 1.0000x reference)
#include <cuda_runtime.h>
#include <cstdint>

#define TOPK     5
#define ROWS     112                 // x rows per CTA -> grid 147 = one CTA/SM, single wave
#define SLOTS    56                  // row slots; each thread handles rows {slot, slot+56}
#define PSPLIT   16                  // p-range split groups
#define PPT      7                   // points per group (16*7 = 112 = padded NP)
#define NP       100
#define NPPAD    112
#define NTHREADS (SLOTS * PSPLIT)    // 896 (28 warps)

#define XS_BYTES  (ROWS * 1024)      // 114688: x tile, swizzled, 1KB row stride
#define RF_BYTES  (NPPAD * 1024)     // 114688: negated ref (+12 pad rows of -1e18)
#define SMEM_BYTES (XS_BYTES + RF_BYTES)   // 229376 B (<= 232448 cap)

typedef unsigned long long u64;

__device__ __forceinline__ u64 f32x2_add(u64 a, u64 b) {
    u64 r; asm("add.rn.f32x2 %0, %1, %2;" : "=l"(r) : "l"(a), "l"(b)); return r;
}
__device__ __forceinline__ u64 f32x2_fma(u64 a, u64 b, u64 c) {
    u64 r; asm("fma.rn.f32x2 %0, %1, %2, %3;" : "=l"(r) : "l"(a), "l"(b), "l"(c)); return r;
}
__device__ __forceinline__ void lds_v2u64(uint32_t addr, u64& a, u64& b) {
    asm volatile("ld.shared.v2.u64 {%0, %1}, [%2];" : "=l"(a), "=l"(b) : "r"(addr));
}
__device__ __forceinline__ float2 unpk(u64 v) {
    float2 f; asm("mov.b64 {%0, %1}, %2;" : "=f"(f.x), "=f"(f.y) : "l"(v)); return f;
}

__device__ __forceinline__ void topk_insert(float dist, int idx, float* bd, int* bi) {
    // ascending p + strict '<'  ==  lax.top_k lowest-index-first tie break
    if (dist < bd[TOPK - 1]) {
        bd[TOPK - 1] = dist; bi[TOPK - 1] = idx;
#pragma unroll
        for (int t = TOPK - 1; t >= 1; --t) {
            if (bd[t] < bd[t - 1]) {
                float tf = bd[t]; bd[t] = bd[t - 1]; bd[t - 1] = tf;
                int   ti = bi[t]; bi[t] = bi[t - 1]; bi[t - 1] = ti;
            }
        }
    }
}

__global__ void __launch_bounds__(NTHREADS)
knn_topk_kernel(const float* __restrict__ x,
                const float* __restrict__ ref,
                float* __restrict__ out,     // indices as float32 (__output__ dtype!)
                int B)
{
    extern __shared__ unsigned char smem[];
    const uint32_t s0 = (uint32_t)__cvta_generic_to_shared(smem);

    const int tid  = threadIdx.x;
    const int row0 = blockIdx.x * ROWS;
    const int nrows = (B - row0) < ROWS ? (B - row0) : ROWS;

    // ---- stage x tile, XOR-swizzled (float4 col c -> c ^ (r&7)) ----
    {
        const float4* x4 = (const float4*)x;
        for (int i = tid; i < ROWS * 64; i += NTHREADS) {
            int rr = i >> 6, c = i & 63;
            if (rr < nrows) {
                uint32_t off = (uint32_t)(rr * 1024) + (uint32_t)((c ^ (rr & 7)) * 16);
                *(float4*)(smem + off) = x4[(size_t)(row0 + rr) * 64 + c];
            }
        }
    }
    // ---- stage NEGATED ref; pad rows 100..111 with -1e18 (dist ~2.6e38, never top-k) ----
    {
        const float4* r4 = (const float4*)ref;
        for (int i = tid; i < NPPAD * 64; i += NTHREADS) {
            int p = i >> 6, c = i & 63;
            float4 v;
            if (p < NP) {
                v = r4[p * 64 + c];
                v.x = -v.x; v.y = -v.y; v.z = -v.z; v.w = -v.w;
            } else {
                v.x = v.y = v.z = v.w = -1e18f;
            }
            *(float4*)(smem + XS_BYTES + (uint32_t)(p * 1024 + c * 16)) = v;
        }
    }
    __syncthreads();

    const int slot = tid % SLOTS;    // rows: slot and slot+56
    const int g    = tid / SLOTS;    // p-split group 0..15 (warp-uniform except straddles)
    const int p0   = g * PPT;

    const int r1 = slot;
    const int r2 = slot + SLOTS;
    const bool v1 = (r1 < nrows);
    const bool v2 = (r2 < nrows);

    const float INF = __int_as_float(0x7f800000);
    float bd1[TOPK], bd2[TOPK]; int bi1[TOPK], bi2[TOPK];
#pragma unroll
    for (int j = 0; j < TOPK; ++j) {
        bd1[j] = INF; bi1[j] = 0; bd2[j] = INF; bi2[j] = 0;
    }

    {
        // r2 = r1 + 56, and 56 % 8 == 0 -> identical swizzle phase for both rows
        const uint32_t xb1  = s0 + (uint32_t)(r1 * 1024);
        const uint32_t xb2  = s0 + (uint32_t)(r2 * 1024);
        const uint32_t xorm = (uint32_t)(slot & 7) << 4;
        const uint32_t rb0  = s0 + XS_BYTES + (uint32_t)(p0 * 1024);

        // acc[2 rows][7 pts][2 classes]; classes (0,1) in A, (2,3) in B.
        u64 aA1[PPT], aB1[PPT], aA2[PPT], aB2[PPT];
#pragma unroll
        for (int pp = 0; pp < PPT; ++pp) {
            aA1[pp] = 0ULL; aB1[pp] = 0ULL; aA2[pp] = 0ULL; aB2[pp] = 0ULL;
        }

#pragma unroll 2
        for (int j = 0; j < 64; ++j) {               // 64 x 16B chunks over D=256
            const uint32_t jo = ((uint32_t)(j * 16)) ^ xorm;
            u64 x1l, x1h, x2l, x2h;
            lds_v2u64(xb1 + jo, x1l, x1h);
            lds_v2u64(xb2 + jo, x2l, x2h);
#pragma unroll
            for (int pp = 0; pp < PPT; ++pp) {
                u64 rl, rh;
                lds_v2u64(rb0 + (uint32_t)(pp * 1024 + j * 16), rl, rh);  // broadcast
                u64 d1l = f32x2_add(x1l, rl);        // row1 (d0,d1) = x + (-r)
                u64 d1h = f32x2_add(x1h, rh);        // row1 (d2,d3)
                aA1[pp] = f32x2_fma(d1l, d1l, aA1[pp]);
                aB1[pp] = f32x2_fma(d1h, d1h, aB1[pp]);
                u64 d2l = f32x2_add(x2l, rl);        // row2
                u64 d2h = f32x2_add(x2h, rh);
                aA2[pp] = f32x2_fma(d2l, d2l, aA2[pp]);
                aB2[pp] = f32x2_fma(d2h, d2h, aB2[pp]);
            }
        }

#pragma unroll
        for (int pp = 0; pp < PPT; ++pp) {           // ascending p
            int idx = p0 + pp;
            float2 a1 = unpk(aA1[pp]); float2 b1 = unpk(aB1[pp]);
            topk_insert((a1.x + a1.y) + (b1.x + b1.y), idx, bd1, bi1);  // R4 exact tree
            float2 a2 = unpk(aA2[pp]); float2 b2 = unpk(aB2[pp]);
            topk_insert((a2.x + a2.y) + (b2.x + b2.y), idx, bd2, bi2);
        }
    }

    // ---- merge 16 partial top-5 lists per row (reuse ref SMEM region) ----
    __syncthreads();
    float* mf = (float*)(smem + XS_BYTES);                           // [15][112][5]
    int*   mi = (int*)(smem + XS_BYTES + (PSPLIT - 1) * ROWS * TOPK * sizeof(float));

    if (g >= 1) {
        int b1o = ((g - 1) * ROWS + r1) * TOPK;
        int b2o = ((g - 1) * ROWS + r2) * TOPK;
#pragma unroll
        for (int j = 0; j < TOPK; ++j) {
            mf[b1o + j] = bd1[j]; mi[b1o + j] = bi1[j];
            mf[b2o + j] = bd2[j]; mi[b2o + j] = bi2[j];
        }
    }
    __syncthreads();

    if (g == 0) {
        for (int gg = 1; gg < PSPLIT; ++gg) {        // ascending group = ascending p
            int b1o = ((gg - 1) * ROWS + r1) * TOPK;
            int b2o = ((gg - 1) * ROWS + r2) * TOPK;
#pragma unroll
            for (int j = 0; j < TOPK; ++j) {
                topk_insert(mf[b1o + j], mi[b1o + j], bd1, bi1);
                topk_insert(mf[b2o + j], mi[b2o + j], bd2, bi2);
            }
        }
        if (v1) {
            float* o = out + (size_t)(row0 + r1) * TOPK;
#pragma unroll
            for (int j = 0; j < TOPK; ++j) o[j] = (float)bi1[j];
        }
        if (v2) {
            float* o = out + (size_t)(row0 + r2) * TOPK;
#pragma unroll
            for (int j = 0; j < TOPK; ++j) o[j] = (float)bi2[j];
        }
    }
}

extern "C" void kernel_launch(void* const* d_in, const int* in_sizes, int n_in,
                              void* d_out, int out_size)
{
    const float* a = (const float*)d_in[0];
    const float* b = (const float*)d_in[1];
    const float* x   = (in_sizes[0] >= in_sizes[1]) ? a : b;
    const float* ref = (in_sizes[0] >= in_sizes[1]) ? b : a;
    int B = out_size / TOPK;                     // 16384

    float* out = (float*)d_out;
    cudaFuncSetAttribute(knn_topk_kernel,
                         cudaFuncAttributeMaxDynamicSharedMemorySize, SMEM_BYTES);
    int grid = (B + ROWS - 1) / ROWS;            // 147 -> one CTA per SM
    knn_topk_kernel<<<grid, NTHREADS, SMEM_BYTES>>>(x, ref, out, B);
}

// round 13
// speedup vs baseline: 1.0939x; 1.0939x over previous
#include <cuda_runtime.h>
#include <cstdint>

#define TOPK     5
#define ROWS     112                 // x rows per CTA -> grid 147 = one CTA/SM
#define GROUPS   8                   // p-split groups; lane layout: row=tid>>3, g=tid&7
#define PPT      13                  // points per group (8*13 = 104)
#define NP       100
#define NPPAD    104
#define NTHREADS (ROWS * GROUPS)     // 896 (28 warps)
#define MARGIN   0.5f                // >> 2x worst-case fp32 score error (~1e-3)

#define XS_BYTES   (ROWS * 1024)     // 114688: x tile, swizzle key = row&7
#define RF_BYTES   (NPPAD * 1024)    // 106496: ref, swizzle key = p/13 (== group)
#define RN_OFF     (XS_BYTES + RF_BYTES)
#define SMEM_BYTES (RN_OFF + NPPAD * 4)   // 221600 B

typedef unsigned long long u64;

__device__ __forceinline__ u64 f32x2_fma(u64 a, u64 b, u64 c) {
    u64 r; asm("fma.rn.f32x2 %0, %1, %2, %3;" : "=l"(r) : "l"(a), "l"(b), "l"(c)); return r;
}
__device__ __forceinline__ void lds_v2u64(uint32_t addr, u64& a, u64& b) {
    asm volatile("ld.shared.v2.u64 {%0, %1}, [%2];" : "=l"(a), "=l"(b) : "r"(addr));
}
__device__ __forceinline__ float2 unpk(u64 v) {
    float2 f; asm("mov.b64 {%0, %1}, %2;" : "=f"(f.x), "=f"(f.y) : "l"(v)); return f;
}

// Merge my ascending 5-list with xor-neighbor's, keep smallest 5 (values only).
__device__ __forceinline__ void bfly_merge_val(float* a, int lx) {
    float b[TOPK];
#pragma unroll
    for (int k = 0; k < TOPK; ++k) b[k] = __shfl_xor_sync(0xffffffffu, a[k], lx);
    float r[TOPK]; int ai = 0, bi = 0;
#pragma unroll
    for (int k = 0; k < TOPK; ++k) {
        bool ta = (bi >= TOPK) || (ai < TOPK && a[ai] <= b[bi]);
        r[k] = ta ? a[ai] : b[bi];
        if (ta) ++ai; else ++bi;
    }
#pragma unroll
    for (int k = 0; k < TOPK; ++k) a[k] = r[k];
}

// Same, for (dist, idx) pairs under lexicographic order.
__device__ __forceinline__ void bfly_merge_pair(float* ad, int* ai_, int lx) {
    float bd[TOPK]; int bi_[TOPK];
#pragma unroll
    for (int k = 0; k < TOPK; ++k) {
        bd[k]  = __shfl_xor_sync(0xffffffffu, ad[k],  lx);
        bi_[k] = __shfl_xor_sync(0xffffffffu, ai_[k], lx);
    }
    float rd[TOPK]; int ri[TOPK]; int ai = 0, bi = 0;
#pragma unroll
    for (int k = 0; k < TOPK; ++k) {
        bool ta = (bi >= TOPK) ||
                  (ai < TOPK && (ad[ai] < bd[bi] ||
                                 (ad[ai] == bd[bi] && ai_[ai] <= bi_[bi])));
        rd[k] = ta ? ad[ai] : bd[bi];
        ri[k] = ta ? ai_[ai] : bi_[bi];
        if (ta) ++ai; else ++bi;
    }
#pragma unroll
    for (int k = 0; k < TOPK; ++k) { ad[k] = rd[k]; ai_[k] = ri[k]; }
}

__global__ void __launch_bounds__(NTHREADS)
knn_topk_kernel(const float* __restrict__ x,
                const float* __restrict__ ref,
                float* __restrict__ out,     // indices as float32 (__output__ dtype!)
                int B)
{
    extern __shared__ unsigned char smem[];
    const uint32_t s0 = (uint32_t)__cvta_generic_to_shared(smem);

    const int tid  = threadIdx.x;
    const int row0 = blockIdx.x * ROWS;
    const int nrows = (B - row0) < ROWS ? (B - row0) : ROWS;

    // ---- stage x tile, swizzle key row&7 (float4 col c -> c ^ (row&7)) ----
    {
        const float4* x4 = (const float4*)x;
        for (int i = tid; i < ROWS * 64; i += NTHREADS) {
            int rr = i >> 6, c = i & 63;
            if (rr < nrows) {
                uint32_t off = (uint32_t)(rr * 1024) + (uint32_t)((c ^ (rr & 7)) * 16);
                *(float4*)(smem + off) = x4[(size_t)(row0 + rr) * 64 + c];
            }
        }
    }
    // ---- stage ref (UNnegated), swizzle key = p/13 (group id); pads = 0 ----
    {
        const float4* r4 = (const float4*)ref;
        for (int i = tid; i < NPPAD * 64; i += NTHREADS) {
            int p = i >> 6, c = i & 63;
            float4 v = make_float4(0.f, 0.f, 0.f, 0.f);
            if (p < NP) v = r4[p * 64 + c];
            int key = (p / PPT) & 7;
            *(float4*)(smem + XS_BYTES + (uint32_t)(p * 1024 + ((c ^ key) * 16))) = v;
        }
    }
    __syncthreads();

    // ---- rnorm2[p] (approx side only); pads forced to +1e30 ----
    if (tid < NPPAD) {
        float rn;
        if (tid < NP) {
            const unsigned char* rrow = smem + XS_BYTES + tid * 1024;
            const uint32_t key = (uint32_t)((tid / PPT) & 7) << 4;
            float a0 = 0.f, a1 = 0.f, a2 = 0.f, a3 = 0.f;
            for (int j = 0; j < 64; ++j) {
                float4 v = *(const float4*)(rrow + (((uint32_t)(j * 16)) ^ key));
                a0 = fmaf(v.x, v.x, a0); a1 = fmaf(v.y, v.y, a1);
                a2 = fmaf(v.z, v.z, a2); a3 = fmaf(v.w, v.w, a3);
            }
            rn = (a0 + a1) + (a2 + a3);
        } else {
            rn = 1e30f;
        }
        *(float*)(smem + RN_OFF + tid * 4) = rn;
    }
    __syncthreads();

    const int row = tid >> 3;        // 0..111
    const int g   = tid & 7;         // group: points g*13 .. g*13+12
    const bool vrow = (row < nrows);

    // ================= Stage A: approx scores (dot trick) =================
    float sc[PPT];
    {
        const uint32_t xbase = s0 + (uint32_t)(row * 1024);
        const uint32_t xkey  = (uint32_t)(row & 7) << 4;
        const uint32_t rbase = s0 + XS_BYTES + (uint32_t)(g * PPT * 1024);
        const uint32_t rkey  = (uint32_t)g << 4;

        u64 acc[PPT];
#pragma unroll
        for (int pp = 0; pp < PPT; ++pp) acc[pp] = 0ULL;

#pragma unroll 4
        for (int j = 0; j < 64; ++j) {
            const uint32_t xo = ((uint32_t)(j * 16)) ^ xkey;
            const uint32_t ro = ((uint32_t)(j * 16)) ^ rkey;
            u64 xl, xh;
            lds_v2u64(xbase + xo, xl, xh);       // 8 lanes/row broadcast
#pragma unroll
            for (int pp = 0; pp < PPT; ++pp) {
                u64 rl, rh;
                lds_v2u64(rbase + (uint32_t)(pp * 1024) + ro, rl, rh);  // 8 distinct/warp
                acc[pp] = f32x2_fma(xl, rl, acc[pp]);
                acc[pp] = f32x2_fma(xh, rh, acc[pp]);
            }
        }
        const float* rn = (const float*)(smem + RN_OFF);
#pragma unroll
        for (int pp = 0; pp < PPT; ++pp) {
            float2 a = unpk(acc[pp]);
            sc[pp] = fmaf(-2.0f, a.x + a.y, rn[g * PPT + pp]);  // ~ dist^2 - ||x||^2
        }
    }

    // ---- per-lane approx top-5 (values), butterfly over the 8 group-lanes ----
    const float INF = __int_as_float(0x7f800000);
    float tau;
    {
        float bd[TOPK];
#pragma unroll
        for (int k = 0; k < TOPK; ++k) bd[k] = INF;
#pragma unroll
        for (int pp = 0; pp < PPT; ++pp) {
            float s = sc[pp];
            if (s < bd[TOPK - 1]) {
                bd[TOPK - 1] = s;
#pragma unroll
                for (int t = TOPK - 1; t >= 1; --t)
                    if (bd[t] < bd[t - 1]) { float tf = bd[t]; bd[t] = bd[t - 1]; bd[t - 1] = tf; }
            }
        }
        bfly_merge_val(bd, 1);
        bfly_merge_val(bd, 2);
        bfly_merge_val(bd, 4);       // all 8 lanes now hold row's approx top-5
        tau = bd[TOPK - 1] + MARGIN;
    }

    // ================= Stage B: exact rescore of candidates =================
    float ed[TOPK]; int ei[TOPK];
#pragma unroll
    for (int k = 0; k < TOPK; ++k) { ed[k] = INF; ei[k] = 0x7fffffff; }

    if (vrow) {
        const unsigned char* xrow = smem + row * 1024;
        const unsigned char* rbas = smem + XS_BYTES;
        const uint32_t xkey = (uint32_t)(row & 7) << 4;
        const uint32_t rkey = (uint32_t)g << 4;

#pragma unroll
        for (int pp = 0; pp < PPT; ++pp) {
            int p = g * PPT + pp;
            if (p < NP && sc[pp] <= tau) {
                const unsigned char* rrow = rbas + p * 1024;
                float a0 = 0.f, a1 = 0.f, a2 = 0.f, a3 = 0.f;
#pragma unroll 4
                for (int j = 0; j < 64; ++j) {
                    float4 xv = *(const float4*)(xrow + (((uint32_t)(j * 16)) ^ xkey));
                    float4 rv = *(const float4*)(rrow + (((uint32_t)(j * 16)) ^ rkey));
                    float d0 = xv.x - rv.x, d1 = xv.y - rv.y;
                    float d2 = xv.z - rv.z, d3 = xv.w - rv.w;
                    a0 = fmaf(d0, d0, a0); a1 = fmaf(d1, d1, a1);
                    a2 = fmaf(d2, d2, a2); a3 = fmaf(d3, d3, a3);
                }
                float dist = (a0 + a1) + (a2 + a3);   // bit-exact R4 tree
                // lexicographic (dist, idx) insert -> exact lax.top_k semantics
                if (dist < ed[TOPK - 1] ||
                    (dist == ed[TOPK - 1] && p < ei[TOPK - 1])) {
                    ed[TOPK - 1] = dist; ei[TOPK - 1] = p;
#pragma unroll
                    for (int t = TOPK - 1; t >= 1; --t) {
                        if (ed[t] < ed[t - 1] ||
                            (ed[t] == ed[t - 1] && ei[t] < ei[t - 1])) {
                            float tf = ed[t]; ed[t] = ed[t - 1]; ed[t - 1] = tf;
                            int   ti = ei[t]; ei[t] = ei[t - 1]; ei[t - 1] = ti;
                        }
                    }
                }
            }
        }
    }

    // ---- butterfly lex-merge over the 8 group-lanes (all lanes participate) ----
    bfly_merge_pair(ed, ei, 1);
    bfly_merge_pair(ed, ei, 2);
    bfly_merge_pair(ed, ei, 4);

    if (g == 0 && vrow) {
        float* o = out + (size_t)(row0 + row) * TOPK;
#pragma unroll
        for (int k = 0; k < TOPK; ++k) o[k] = (float)ei[k];
    }
}

extern "C" void kernel_launch(void* const* d_in, const int* in_sizes, int n_in,
                              void* d_out, int out_size)
{
    const float* a = (const float*)d_in[0];
    const float* b = (const float*)d_in[1];
    const float* x   = (in_sizes[0] >= in_sizes[1]) ? a : b;
    const float* ref = (in_sizes[0] >= in_sizes[1]) ? b : a;
    int B = out_size / TOPK;                     // 16384

    float* out = (float*)d_out;
    cudaFuncSetAttribute(knn_topk_kernel,
                         cudaFuncAttributeMaxDynamicSharedMemorySize, SMEM_BYTES);
    int grid = (B + ROWS - 1) / ROWS;            // 147 -> one CTA per SM
    knn_topk_kernel<<<grid, NTHREADS, SMEM_BYTES>>>(x, ref, out, B);
}

// round 14
// speedup vs baseline: 2.7495x; 2.5134x over previous
#include <cuda_runtime.h>
#include <cstdint>

#define TOPK     5
#define ROWS     112                 // x rows per CTA -> grid 147 = one CTA/SM
#define SLOTS    56                  // row slots; thread handles rows {slot, slot+56}
#define PSPLIT   8                   // p-range split groups
#define PPT      13                  // points per group (8*13 = 104 = padded NP)
#define NP       100
#define NPPAD    104
#define NTHREADS (SLOTS * PSPLIT)    // 448 (14 warps) -> reg cap 146/thread (no spill)

#define XS_BYTES  (ROWS * 1024)      // 114688: x tile, swizzled, 1KB row stride
#define RF_BYTES  (NPPAD * 1024)     // 106496: negated ref (+4 pad rows of -1e18)
#define SMEM_BYTES (XS_BYTES + RF_BYTES)   // 221184 B

typedef unsigned long long u64;

__device__ __forceinline__ u64 f32x2_add(u64 a, u64 b) {
    u64 r; asm("add.rn.f32x2 %0, %1, %2;" : "=l"(r) : "l"(a), "l"(b)); return r;
}
__device__ __forceinline__ u64 f32x2_fma(u64 a, u64 b, u64 c) {
    u64 r; asm("fma.rn.f32x2 %0, %1, %2, %3;" : "=l"(r) : "l"(a), "l"(b), "l"(c)); return r;
}
__device__ __forceinline__ void lds_v2u64(uint32_t addr, u64& a, u64& b) {
    asm volatile("ld.shared.v2.u64 {%0, %1}, [%2];" : "=l"(a), "=l"(b) : "r"(addr));
}
__device__ __forceinline__ float2 unpk(u64 v) {
    float2 f; asm("mov.b64 {%0, %1}, %2;" : "=f"(f.x), "=f"(f.y) : "l"(v)); return f;
}

__device__ __forceinline__ void topk_insert(float dist, int idx, float* bd, int* bi) {
    // ascending p + strict '<'  ==  lax.top_k lowest-index-first tie break
    if (dist < bd[TOPK - 1]) {
        bd[TOPK - 1] = dist; bi[TOPK - 1] = idx;
#pragma unroll
        for (int t = TOPK - 1; t >= 1; --t) {
            if (bd[t] < bd[t - 1]) {
                float tf = bd[t]; bd[t] = bd[t - 1]; bd[t - 1] = tf;
                int   ti = bi[t]; bi[t] = bi[t - 1]; bi[t - 1] = ti;
            }
        }
    }
}

// Diff-square for PB points x 2 rows; per-(row,point) accumulation is the
// PROVEN bit-exact tree: accA lanes = classes (0,1), accB = (2,3), ascending j.
template<int PB>
__device__ __forceinline__ void compute_block2(
    uint32_t xb1, uint32_t xb2, uint32_t xorm, uint32_t rb0, int pbase,
    float* bd1, int* bi1, float* bd2, int* bi2)
{
    u64 aA1[PB], aB1[PB], aA2[PB], aB2[PB];
#pragma unroll
    for (int pp = 0; pp < PB; ++pp) {
        aA1[pp] = 0ULL; aB1[pp] = 0ULL; aA2[pp] = 0ULL; aB2[pp] = 0ULL;
    }

#pragma unroll 2
    for (int j = 0; j < 64; ++j) {               // 64 x 16B chunks over D=256
        const uint32_t jo = ((uint32_t)(j * 16)) ^ xorm;
        u64 x1l, x1h, x2l, x2h;
        lds_v2u64(xb1 + jo, x1l, x1h);
        lds_v2u64(xb2 + jo, x2l, x2h);
#pragma unroll
        for (int pp = 0; pp < PB; ++pp) {
            u64 rl, rh;
            lds_v2u64(rb0 + (uint32_t)(pp * 1024 + j * 16), rl, rh);  // broadcast, 2 rows
            u64 d1l = f32x2_add(x1l, rl);        // row1 (d0,d1) = x + (-r)
            u64 d1h = f32x2_add(x1h, rh);        // row1 (d2,d3)
            aA1[pp] = f32x2_fma(d1l, d1l, aA1[pp]);
            aB1[pp] = f32x2_fma(d1h, d1h, aB1[pp]);
            u64 d2l = f32x2_add(x2l, rl);        // row2
            u64 d2h = f32x2_add(x2h, rh);
            aA2[pp] = f32x2_fma(d2l, d2l, aA2[pp]);
            aB2[pp] = f32x2_fma(d2h, d2h, aB2[pp]);
        }
    }

#pragma unroll
    for (int pp = 0; pp < PB; ++pp) {            // ascending p
        int idx = pbase + pp;
        float2 a1 = unpk(aA1[pp]); float2 b1 = unpk(aB1[pp]);
        topk_insert((a1.x + a1.y) + (b1.x + b1.y), idx, bd1, bi1);   // R4 exact tree
        float2 a2 = unpk(aA2[pp]); float2 b2 = unpk(aB2[pp]);
        topk_insert((a2.x + a2.y) + (b2.x + b2.y), idx, bd2, bi2);
    }
}

__global__ void __launch_bounds__(NTHREADS)
knn_topk_kernel(const float* __restrict__ x,
                const float* __restrict__ ref,
                float* __restrict__ out,     // indices as float32 (__output__ dtype!)
                int B)
{
    extern __shared__ unsigned char smem[];
    const uint32_t s0 = (uint32_t)__cvta_generic_to_shared(smem);

    const int tid  = threadIdx.x;
    const int row0 = blockIdx.x * ROWS;
    const int nrows = (B - row0) < ROWS ? (B - row0) : ROWS;

    // ---- stage x tile, XOR-swizzled (float4 col c -> c ^ (r&7)) ----
    {
        const float4* x4 = (const float4*)x;
        for (int i = tid; i < ROWS * 64; i += NTHREADS) {
            int rr = i >> 6, c = i & 63;
            if (rr < nrows) {
                uint32_t off = (uint32_t)(rr * 1024) + (uint32_t)((c ^ (rr & 7)) * 16);
                *(float4*)(smem + off) = x4[(size_t)(row0 + rr) * 64 + c];
            }
        }
    }
    // ---- stage NEGATED ref; pad rows 100..103 with -1e18 (never in top-k) ----
    {
        const float4* r4 = (const float4*)ref;
        for (int i = tid; i < NPPAD * 64; i += NTHREADS) {
            int p = i >> 6, c = i & 63;
            float4 v;
            if (p < NP) {
                v = r4[p * 64 + c];
                v.x = -v.x; v.y = -v.y; v.z = -v.z; v.w = -v.w;
            } else {
                v.x = v.y = v.z = v.w = -1e18f;
            }
            *(float4*)(smem + XS_BYTES + (uint32_t)(p * 1024 + c * 16)) = v;
        }
    }
    __syncthreads();

    const int slot = tid % SLOTS;    // rows: slot and slot+56 (same swizzle phase)
    const int g    = tid / SLOTS;    // p-split group 0..7
    const int p0   = g * PPT;

    const int r1 = slot;
    const int r2 = slot + SLOTS;

    const float INF = __int_as_float(0x7f800000);
    float bd1[TOPK], bd2[TOPK]; int bi1[TOPK], bi2[TOPK];
#pragma unroll
    for (int j = 0; j < TOPK; ++j) {
        bd1[j] = INF; bi1[j] = 0; bd2[j] = INF; bi2[j] = 0;
    }

    {
        const uint32_t xb1  = s0 + (uint32_t)(r1 * 1024);
        const uint32_t xb2  = s0 + (uint32_t)(r2 * 1024);
        const uint32_t xorm = (uint32_t)(slot & 7) << 4;   // 56%8==0: shared by both rows
        const uint32_t rb0  = s0 + XS_BYTES + (uint32_t)(p0 * 1024);

        compute_block2<7>(xb1, xb2, xorm, rb0,              p0,     bd1, bi1, bd2, bi2);
        compute_block2<6>(xb1, xb2, xorm, rb0 + 7u * 1024u, p0 + 7, bd1, bi1, bd2, bi2);
    }

    // ---- merge 8 partial top-5 lists per row (reuse ref SMEM region) ----
    __syncthreads();
    float* mf = (float*)(smem + XS_BYTES);                           // [7][112][5]
    int*   mi = (int*)(smem + XS_BYTES + (PSPLIT - 1) * ROWS * TOPK * sizeof(float));

    if (g >= 1) {
        int b1o = ((g - 1) * ROWS + r1) * TOPK;
        int b2o = ((g - 1) * ROWS + r2) * TOPK;
#pragma unroll
        for (int j = 0; j < TOPK; ++j) {
            mf[b1o + j] = bd1[j]; mi[b1o + j] = bi1[j];
            mf[b2o + j] = bd2[j]; mi[b2o + j] = bi2[j];
        }
    }
    __syncthreads();

    if (g == 0) {
        for (int gg = 1; gg < PSPLIT; ++gg) {        // ascending group = ascending p
            int b1o = ((gg - 1) * ROWS + r1) * TOPK;
            int b2o = ((gg - 1) * ROWS + r2) * TOPK;
#pragma unroll
            for (int j = 0; j < TOPK; ++j) {
                topk_insert(mf[b1o + j], mi[b1o + j], bd1, bi1);
                topk_insert(mf[b2o + j], mi[b2o + j], bd2, bi2);
            }
        }
        if (r1 < nrows) {
            float* o = out + (size_t)(row0 + r1) * TOPK;
#pragma unroll
            for (int j = 0; j < TOPK; ++j) o[j] = (float)bi1[j];
        }
        if (r2 < nrows) {
            float* o = out + (size_t)(row0 + r2) * TOPK;
#pragma unroll
            for (int j = 0; j < TOPK; ++j) o[j] = (float)bi2[j];
        }
    }
}

extern "C" void kernel_launch(void* const* d_in, const int* in_sizes, int n_in,
                              void* d_out, int out_size)
{
    const float* a = (const float*)d_in[0];
    const float* b = (const float*)d_in[1];
    const float* x   = (in_sizes[0] >= in_sizes[1]) ? a : b;
    const float* ref = (in_sizes[0] >= in_sizes[1]) ? b : a;
    int B = out_size / TOPK;                     // 16384

    float* out = (float*)d_out;
    cudaFuncSetAttribute(knn_topk_kernel,
                         cudaFuncAttributeMaxDynamicSharedMemorySize, SMEM_BYTES);
    int grid = (B + ROWS - 1) / ROWS;            // 147 -> one CTA per SM
    knn_topk_kernel<<<grid, NTHREADS, SMEM_BYTES>>>(x, ref, out, B);
}